// round 3
// baseline (speedup 1.0000x reference)
#include <cuda_runtime.h>
#include <math.h>
#include <float.h>

// Problem constants
#define BB 2
#define N1 16384
#define N2 4096
#define C1 128
#define C2 256
#define M_OUT 256          // output channels of both linear layers
#define K1 384
#define K2 256
#define TOT (BB * M_OUT * N1)   // 8,388,608 elements per activation tensor

// ---------------- device scratch (no allocations allowed) ----------------
__device__ float g_x2t[BB * N2 * C2];       // x2 transposed: (B, N2, C2)   8 MB
__device__ int   g_idx[BB * N1 * 3];        // knn indices
__device__ float g_w[BB * N1 * 3];          // knn weights (normalized)
__device__ float g_interp_t[BB * N1 * C2];  // interpolated feats, (B, N1, C2) 33.5 MB
__device__ float g_y1[BB * M_OUT * N1];     // layer-1 activations (B, 256, N1) 33.5 MB
__device__ float g_scale[M_OUT];
__device__ float g_shift[M_OUT];

// ---------------- packed f32x2 helpers (Blackwell FFMA2) ----------------
#define DUP2(D, S) asm("mov.b64 %0, {%1, %1};" : "=l"(D) : "f"(S))
#define FMA2(ACC, A, BV) \
    asm("fma.rn.f32x2 %0, %1, %2, %0;" : "+l"(ACC) : "l"(A), "l"(BV))

// =========================================================================
// 1) KNN — replicates the reference's distance arithmetic EXACTLY:
//    d = (|q|^2 + |r|^2) - 2*(q·r), with plain-rounded sums of squares and
//    an FMA-chain dot product, then clamp to >= 0.
//    Refs processed in 2 chunks of 2048 (32 KB static smem, float4-packed).
// =========================================================================
#define KNN_CHUNK 2048

__global__ void __launch_bounds__(128) knn_kernel(const float* __restrict__ p1,
                                                  const float* __restrict__ p2)
{
    __shared__ float4 s[KNN_CHUNK];   // {x, y, z, bb}  32 KB

    const int b = blockIdx.y;
    const int n = blockIdx.x * 128 + threadIdx.x;

    const size_t qoff = ((size_t)b * N1 + n) * 3;
    const float qx = p1[qoff + 0];
    const float qy = p1[qoff + 1];
    const float qz = p1[qoff + 2];
    float tq = __fadd_rn(__fmul_rn(qx, qx), __fmul_rn(qy, qy));
    const float qq = __fadd_rn(tq, __fmul_rn(qz, qz));

    float d0 = FLT_MAX, d1 = FLT_MAX, d2 = FLT_MAX;
    int   i0 = 0,       i1 = 0,       i2 = 0;

    const float* p2b = p2 + (size_t)b * N2 * 3;

    #pragma unroll
    for (int chunk = 0; chunk < N2 / KNN_CHUNK; ++chunk) {
        if (chunk > 0) __syncthreads();
        const int jbase = chunk * KNN_CHUNK;
        for (int j = threadIdx.x; j < KNN_CHUNK; j += 128) {
            float x = p2b[(jbase + j) * 3 + 0];
            float y = p2b[(jbase + j) * 3 + 1];
            float z = p2b[(jbase + j) * 3 + 2];
            // bb = ((x*x + y*y) + z*z), round-to-nearest each step, NO contraction
            float t  = __fadd_rn(__fmul_rn(x, x), __fmul_rn(y, y));
            float bb = __fadd_rn(t, __fmul_rn(z, z));
            s[j] = make_float4(x, y, z, bb);
        }
        __syncthreads();

        #pragma unroll 4
        for (int j = 0; j < KNN_CHUNK; ++j) {
            float4 r = s[j];
            // dot as sequential-k fma chain
            float dot = __fmaf_rn(qz, r.z, __fmaf_rn(qy, r.y, __fmul_rn(qx, r.x)));
            // d = (qq + bb) - 2*dot, matching "aa + bb - 2.0*einsum"
            float d = __fsub_rn(__fadd_rn(qq, r.w), __fmul_rn(2.0f, dot));
            if (d < d2) {
                const int jg = jbase + j;
                if (d < d1) {
                    d2 = d1; i2 = i1;
                    if (d < d0) { d1 = d0; i1 = i0; d0 = d; i0 = jg; }
                    else        { d1 = d;  i1 = jg; }
                } else {
                    d2 = d; i2 = jg;
                }
            }
        }
    }

    // dist = max(d, 0); w = 1/(dist + 1e-16); normalize
    d0 = fmaxf(d0, 0.0f);
    d1 = fmaxf(d1, 0.0f);
    d2 = fmaxf(d2, 0.0f);
    float w0 = 1.f / (d0 + 1e-16f);
    float w1 = 1.f / (d1 + 1e-16f);
    float w2 = 1.f / (d2 + 1e-16f);
    float ws = 1.f / (w0 + w1 + w2);

    const int base = (b * N1 + n) * 3;
    g_w[base + 0] = w0 * ws;
    g_w[base + 1] = w1 * ws;
    g_w[base + 2] = w2 * ws;
    g_idx[base + 0] = i0;
    g_idx[base + 1] = i1;
    g_idx[base + 2] = i2;
}

// =========================================================================
// 2) Transpose x2 (B, C2, N2) -> (B, N2, C2) for coalesced gathers
// =========================================================================
__global__ void transpose_x2_kernel(const float* __restrict__ x2)
{
    __shared__ float tile[32][33];
    const int b  = blockIdx.z;
    const int c0 = blockIdx.y * 32;
    const int n0 = blockIdx.x * 32;
    const int tx = threadIdx.x;
    const int ty = threadIdx.y;   // 0..7

    #pragma unroll
    for (int i = ty; i < 32; i += 8)
        tile[i][tx] = x2[((size_t)b * C2 + c0 + i) * N2 + n0 + tx];
    __syncthreads();
    #pragma unroll
    for (int i = ty; i < 32; i += 8)
        g_x2t[((size_t)b * N2 + n0 + i) * C2 + c0 + tx] = tile[tx][i];
}

// =========================================================================
// 3) Gather + weighted sum: one warp per query, coalesced reads & writes
//    output layout (B, N1, C2)
// =========================================================================
__global__ void __launch_bounds__(256) gather_interp_kernel()
{
    const int q    = blockIdx.x * 8 + (threadIdx.x >> 5);  // global query id
    const int lane = threadIdx.x & 31;
    if (q >= BB * N1) return;
    const int b = q / N1;
    const int n = q % N1;

    const int base = q * 3;
    const float w0 = g_w[base + 0];
    const float w1 = g_w[base + 1];
    const float w2 = g_w[base + 2];
    const float* f0 = g_x2t + ((size_t)b * N2 + g_idx[base + 0]) * C2;
    const float* f1 = g_x2t + ((size_t)b * N2 + g_idx[base + 1]) * C2;
    const float* f2 = g_x2t + ((size_t)b * N2 + g_idx[base + 2]) * C2;
    float* o = g_interp_t + ((size_t)b * N1 + n) * C2;

    #pragma unroll
    for (int c = lane; c < C2; c += 32)
        o[c] = fmaf(w0, f0[c], fmaf(w1, f1[c], w2 * f2[c]));
}

// =========================================================================
// 4) FP32 GEMM with f32x2 packed FMAs.
//    Y[b, m, n] = sum_k W[m,k] * X[b,k,n] + bias[m]
//    X rows k <  KSPLIT come from XA with layout (B, KSPLIT, N1) (n-contig)
//    X rows k >= KSPLIT come from XB with layout (B, N1, K-KSPLIT) (k-contig)
//    Tile: 64(m) x 64(n), BK=16, 128 threads, thread tile 4m x 8n.
// =========================================================================
template<int K, int KSPLIT>
__global__ void __launch_bounds__(128) gemm_kernel(
    const float* __restrict__ W, const float* __restrict__ bias,
    const float* __restrict__ XA, const float* __restrict__ XB,
    float* __restrict__ Y)
{
    const int b  = blockIdx.z;
    const int n0 = blockIdx.x * 64;
    const int m0 = blockIdx.y * 64;

    __shared__ __align__(16) float As[2][16][64];
    __shared__ __align__(16) float Bs[2][16][64];

    const int tid = threadIdx.x;
    const int tn  = tid & 7;    // 8 n-groups (8 wide)
    const int tm  = tid >> 3;   // 16 m-groups (4 tall)

    unsigned long long acc[4][4];
    #pragma unroll
    for (int i = 0; i < 4; i++)
        #pragma unroll
        for (int j = 0; j < 4; j++) acc[i][j] = 0ULL;

    const float* XAb = XA + (size_t)b * KSPLIT * N1;
    const float* XBb = (KSPLIT < K) ? (XB + (size_t)b * N1 * (K - KSPLIT)) : XA;

    auto load_tile = [&](int kt, int buf) {
        const int k0 = kt * 16;
        // ---- As: transposed W tile ----
        #pragma unroll
        for (int r = 0; r < 2; r++) {
            const int ii = tid + r * 128;     // 0..255
            const int ml = ii >> 2;           // 0..63
            const int k4 = ii & 3;            // 0..3
            float4 w4 = *(const float4*)&W[(size_t)(m0 + ml) * K + k0 + k4 * 4];
            As[buf][k4 * 4 + 0][ml] = w4.x;
            As[buf][k4 * 4 + 1][ml] = w4.y;
            As[buf][k4 * 4 + 2][ml] = w4.z;
            As[buf][k4 * 4 + 3][ml] = w4.w;
        }
        // ---- Bs ----
        if (k0 < KSPLIT) {
            #pragma unroll
            for (int r = 0; r < 2; r++) {
                const int ii = tid + r * 128;
                const int kl = ii >> 4;       // 0..15
                const int n4 = ii & 15;       // 0..15
                float4 v = *(const float4*)&XAb[(size_t)(k0 + kl) * N1 + n0 + n4 * 4];
                *(float4*)&Bs[buf][kl][n4 * 4] = v;
            }
        } else {
            const int CB = (K - KSPLIT) > 0 ? (K - KSPLIT) : 1;
            #pragma unroll
            for (int r = 0; r < 2; r++) {
                const int ii = tid + r * 128;
                const int nl = ii >> 2;       // 0..63
                const int k4 = ii & 3;
                float4 v = *(const float4*)&XBb[(size_t)(n0 + nl) * CB + (k0 - KSPLIT) + k4 * 4];
                Bs[buf][k4 * 4 + 0][nl] = v.x;
                Bs[buf][k4 * 4 + 1][nl] = v.y;
                Bs[buf][k4 * 4 + 2][nl] = v.z;
                Bs[buf][k4 * 4 + 3][nl] = v.w;
            }
        }
    };

    constexpr int NT = K / 16;
    load_tile(0, 0);
    __syncthreads();

    for (int t = 0; t < NT; ++t) {
        if (t + 1 < NT) load_tile(t + 1, (t + 1) & 1);
        const int buf = t & 1;
        #pragma unroll
        for (int kk = 0; kk < 16; ++kk) {
            float4 a4 = *(const float4*)&As[buf][kk][tm * 4];
            ulonglong2 b01 = *(const ulonglong2*)&Bs[buf][kk][tn * 8];
            ulonglong2 b23 = *(const ulonglong2*)&Bs[buf][kk][tn * 8 + 4];
            unsigned long long av;
            DUP2(av, a4.x);
            FMA2(acc[0][0], av, b01.x); FMA2(acc[0][1], av, b01.y);
            FMA2(acc[0][2], av, b23.x); FMA2(acc[0][3], av, b23.y);
            DUP2(av, a4.y);
            FMA2(acc[1][0], av, b01.x); FMA2(acc[1][1], av, b01.y);
            FMA2(acc[1][2], av, b23.x); FMA2(acc[1][3], av, b23.y);
            DUP2(av, a4.z);
            FMA2(acc[2][0], av, b01.x); FMA2(acc[2][1], av, b01.y);
            FMA2(acc[2][2], av, b23.x); FMA2(acc[2][3], av, b23.y);
            DUP2(av, a4.w);
            FMA2(acc[3][0], av, b01.x); FMA2(acc[3][1], av, b01.y);
            FMA2(acc[3][2], av, b23.x); FMA2(acc[3][3], av, b23.y);
        }
        __syncthreads();
    }

    // epilogue: + bias, store
    #pragma unroll
    for (int i = 0; i < 4; i++) {
        const int m = m0 + tm * 4 + i;
        const float bi = bias[m];
        float* yrow = Y + ((size_t)b * M_OUT + m) * N1 + n0 + tn * 8;
        #pragma unroll
        for (int j = 0; j < 4; j++) {
            float lo = __uint_as_float((unsigned)(acc[i][j] & 0xffffffffULL));
            float hi = __uint_as_float((unsigned)(acc[i][j] >> 32));
            float2 v = make_float2(lo + bi, hi + bi);
            *(float2*)&yrow[j * 2] = v;
        }
    }
}

// =========================================================================
// 5) BN stats: per channel, mean/var over (B, N) -> scale/shift
// =========================================================================
__global__ void __launch_bounds__(256) bn_stats_kernel(const float* __restrict__ Y,
                                                       const float* __restrict__ gamma,
                                                       const float* __restrict__ beta)
{
    const int o = blockIdx.x;
    const int t = threadIdx.x;
    float s = 0.f, ss = 0.f;
    #pragma unroll
    for (int b = 0; b < BB; ++b) {
        const float* p = Y + ((size_t)b * M_OUT + o) * N1;
        for (int n = t; n < N1; n += 256) {
            float v = p[n];
            s += v;
            ss = fmaf(v, v, ss);
        }
    }
    __shared__ float sh[256], sh2[256];
    sh[t] = s; sh2[t] = ss;
    __syncthreads();
    for (int st = 128; st > 0; st >>= 1) {
        if (t < st) { sh[t] += sh[t + st]; sh2[t] += sh2[t + st]; }
        __syncthreads();
    }
    if (t == 0) {
        const float inv = 1.f / (float)(BB * N1);
        float mu  = sh[0] * inv;
        float var = sh2[0] * inv - mu * mu;
        float sc  = gamma[o] * rsqrtf(var + 1e-5f);
        g_scale[o] = sc;
        g_shift[o] = fmaf(-mu, sc, beta[o]);
    }
}

// =========================================================================
// 6) BN apply + ReLU, in place, vectorized
// =========================================================================
__global__ void __launch_bounds__(256) bn_apply_kernel(float* __restrict__ Y)
{
    const size_t base = ((size_t)blockIdx.x * 256 + threadIdx.x) * 4;
    if (base >= (size_t)TOT) return;
    const int o = (int)((base / N1) % M_OUT);
    const float sc = g_scale[o];
    const float sf = g_shift[o];
    float4 v = *(float4*)&Y[base];
    v.x = fmaxf(fmaf(v.x, sc, sf), 0.f);
    v.y = fmaxf(fmaf(v.y, sc, sf), 0.f);
    v.z = fmaxf(fmaf(v.z, sc, sf), 0.f);
    v.w = fmaxf(fmaf(v.w, sc, sf), 0.f);
    *(float4*)&Y[base] = v;
}

// =========================================================================
// launcher
// =========================================================================
extern "C" void kernel_launch(void* const* d_in, const int* in_sizes, int n_in,
                              void* d_out, int out_size)
{
    const float* p1  = (const float*)d_in[0];
    const float* x1  = (const float*)d_in[1];
    const float* p2  = (const float*)d_in[2];
    const float* x2  = (const float*)d_in[3];
    const float* W1  = (const float*)d_in[4];
    const float* b1  = (const float*)d_in[5];
    const float* g1  = (const float*)d_in[6];
    const float* be1 = (const float*)d_in[7];
    const float* W2  = (const float*)d_in[8];
    const float* b2  = (const float*)d_in[9];
    const float* g2  = (const float*)d_in[10];
    const float* be2 = (const float*)d_in[11];
    float* out = (float*)d_out;

    float* interp_t; cudaGetSymbolAddress((void**)&interp_t, g_interp_t);
    float* y1;       cudaGetSymbolAddress((void**)&y1, g_y1);

    // 1) KNN indices + weights
    knn_kernel<<<dim3(N1 / 128, BB), 128>>>(p1, p2);
    // 2) transpose x2
    transpose_x2_kernel<<<dim3(N2 / 32, C2 / 32, BB), dim3(32, 8)>>>(x2);
    // 3) gather interpolated features (B, N1, C2)
    gather_interp_kernel<<<(BB * N1) / 8, 256>>>();
    // 4) GEMM1: [x1 ; interp] -> y1
    gemm_kernel<K1, C1><<<dim3(N1 / 64, M_OUT / 64, BB), 128>>>(W1, b1, x1, interp_t, y1);
    // 5) BN1 + ReLU
    bn_stats_kernel<<<M_OUT, 256>>>(y1, g1, be1);
    bn_apply_kernel<<<TOT / 1024, 256>>>(y1);
    // 6) GEMM2: y1 -> out
    gemm_kernel<K2, K2><<<dim3(N1 / 64, M_OUT / 64, BB), 128>>>(W2, b2, y1, nullptr, out);
    // 7) BN2 + ReLU
    bn_stats_kernel<<<M_OUT, 256>>>(out, g2, be2);
    bn_apply_kernel<<<TOT / 1024, 256>>>(out);
}

// round 4
// speedup vs baseline: 1.2460x; 1.2460x over previous
#include <cuda_runtime.h>
#include <math.h>
#include <float.h>

// Problem constants
#define BB 2
#define N1 16384
#define N2 4096
#define C1 128
#define C2 256
#define M_OUT 256
#define K1 384
#define K2 256
#define TOT (BB * M_OUT * N1)

// ---------------- device scratch ----------------
__device__ float g_x2t[BB * N2 * C2];
__device__ int   g_idx[BB * N1 * 3];
__device__ float g_w[BB * N1 * 3];
__device__ float g_interp_t[BB * N1 * C2];
__device__ float g_y1[BB * M_OUT * N1];
__device__ float g_scale[M_OUT];
__device__ float g_shift[M_OUT];

// ---------------- packed f32x2 helpers ----------------
#define DUP2(D, S) asm("mov.b64 %0, {%1, %1};" : "=l"(D) : "f"(S))
#define FMA2(ACC, A, BV) \
    asm("fma.rn.f32x2 %0, %1, %2, %0;" : "+l"(ACC) : "l"(A), "l"(BV))

// =========================================================================
// 1) KNN — reference-exact distance arithmetic, 2 chunks of 2048 refs
// =========================================================================
#define KNN_CHUNK 2048

__global__ void __launch_bounds__(128) knn_kernel(const float* __restrict__ p1,
                                                  const float* __restrict__ p2)
{
    __shared__ float4 s[KNN_CHUNK];   // {x, y, z, bb}  32 KB

    const int b = blockIdx.y;
    const int n = blockIdx.x * 128 + threadIdx.x;

    const size_t qoff = ((size_t)b * N1 + n) * 3;
    const float qx = p1[qoff + 0];
    const float qy = p1[qoff + 1];
    const float qz = p1[qoff + 2];
    float tq = __fadd_rn(__fmul_rn(qx, qx), __fmul_rn(qy, qy));
    const float qq = __fadd_rn(tq, __fmul_rn(qz, qz));

    float d0 = FLT_MAX, d1 = FLT_MAX, d2 = FLT_MAX;
    int   i0 = 0,       i1 = 0,       i2 = 0;

    const float* p2b = p2 + (size_t)b * N2 * 3;

    #pragma unroll
    for (int chunk = 0; chunk < N2 / KNN_CHUNK; ++chunk) {
        if (chunk > 0) __syncthreads();
        const int jbase = chunk * KNN_CHUNK;
        for (int j = threadIdx.x; j < KNN_CHUNK; j += 128) {
            float x = p2b[(jbase + j) * 3 + 0];
            float y = p2b[(jbase + j) * 3 + 1];
            float z = p2b[(jbase + j) * 3 + 2];
            float t  = __fadd_rn(__fmul_rn(x, x), __fmul_rn(y, y));
            float bb = __fadd_rn(t, __fmul_rn(z, z));
            s[j] = make_float4(x, y, z, bb);
        }
        __syncthreads();

        #pragma unroll 4
        for (int j = 0; j < KNN_CHUNK; ++j) {
            float4 r = s[j];
            float dot = __fmaf_rn(qz, r.z, __fmaf_rn(qy, r.y, __fmul_rn(qx, r.x)));
            float d = __fsub_rn(__fadd_rn(qq, r.w), __fmul_rn(2.0f, dot));
            if (d < d2) {
                const int jg = jbase + j;
                if (d < d1) {
                    d2 = d1; i2 = i1;
                    if (d < d0) { d1 = d0; i1 = i0; d0 = d; i0 = jg; }
                    else        { d1 = d;  i1 = jg; }
                } else {
                    d2 = d; i2 = jg;
                }
            }
        }
    }

    d0 = fmaxf(d0, 0.0f);
    d1 = fmaxf(d1, 0.0f);
    d2 = fmaxf(d2, 0.0f);
    float w0 = 1.f / (d0 + 1e-16f);
    float w1 = 1.f / (d1 + 1e-16f);
    float w2 = 1.f / (d2 + 1e-16f);
    float ws = 1.f / (w0 + w1 + w2);

    const int base = (b * N1 + n) * 3;
    g_w[base + 0] = w0 * ws;
    g_w[base + 1] = w1 * ws;
    g_w[base + 2] = w2 * ws;
    g_idx[base + 0] = i0;
    g_idx[base + 1] = i1;
    g_idx[base + 2] = i2;
}

// =========================================================================
// 2) Transpose x2 (B, C2, N2) -> (B, N2, C2)
// =========================================================================
__global__ void transpose_x2_kernel(const float* __restrict__ x2)
{
    __shared__ float tile[32][33];
    const int b  = blockIdx.z;
    const int c0 = blockIdx.y * 32;
    const int n0 = blockIdx.x * 32;
    const int tx = threadIdx.x;
    const int ty = threadIdx.y;

    #pragma unroll
    for (int i = ty; i < 32; i += 8)
        tile[i][tx] = x2[((size_t)b * C2 + c0 + i) * N2 + n0 + tx];
    __syncthreads();
    #pragma unroll
    for (int i = ty; i < 32; i += 8)
        g_x2t[((size_t)b * N2 + n0 + i) * C2 + c0 + tx] = tile[tx][i];
}

// =========================================================================
// 3) Gather + weighted sum (one warp per query) -> (B, N1, C2)
// =========================================================================
__global__ void __launch_bounds__(256) gather_interp_kernel()
{
    const int q    = blockIdx.x * 8 + (threadIdx.x >> 5);
    const int lane = threadIdx.x & 31;
    if (q >= BB * N1) return;
    const int b = q / N1;
    const int n = q % N1;

    const int base = q * 3;
    const float w0 = g_w[base + 0];
    const float w1 = g_w[base + 1];
    const float w2 = g_w[base + 2];
    const float* f0 = g_x2t + ((size_t)b * N2 + g_idx[base + 0]) * C2;
    const float* f1 = g_x2t + ((size_t)b * N2 + g_idx[base + 1]) * C2;
    const float* f2 = g_x2t + ((size_t)b * N2 + g_idx[base + 2]) * C2;
    float* o = g_interp_t + ((size_t)b * N1 + n) * C2;

    #pragma unroll
    for (int c = lane; c < C2; c += 32)
        o[c] = fmaf(w0, f0[c], fmaf(w1, f1[c], w2 * f2[c]));
}

// =========================================================================
// 4) FP32 GEMM, f32x2 packed FMAs, 128(m) x 64(n) tile, BK=16,
//    128 threads, 8m x 8n per thread.
//    XA: (B, KSPLIT, N1) n-contig  |  XB: (B, N1, K-KSPLIT) k-contig
//    BN_A: apply g_scale/g_shift + ReLU to XA elements on load (channel = k)
// =========================================================================
template<int K, int KSPLIT, bool BN_A>
__global__ void __launch_bounds__(128) gemm_kernel(
    const float* __restrict__ W, const float* __restrict__ bias,
    const float* __restrict__ XA, const float* __restrict__ XB,
    float* __restrict__ Y)
{
    const int b  = blockIdx.z;
    const int n0 = blockIdx.x * 64;
    const int m0 = blockIdx.y * 128;

    __shared__ __align__(16) float As[2][16][128];  // 16 KB
    __shared__ __align__(16) float Bs[2][16][64];   //  8 KB

    const int tid = threadIdx.x;
    const int tn  = tid & 7;    // 8 n-groups of 8
    const int tm  = tid >> 3;   // 16 m-groups of 8

    unsigned long long acc[8][4];
    #pragma unroll
    for (int i = 0; i < 8; i++)
        #pragma unroll
        for (int j = 0; j < 4; j++) acc[i][j] = 0ULL;

    const float* XAb = XA + (size_t)b * KSPLIT * N1;
    const float* XBb = (KSPLIT < K) ? (XB + (size_t)b * N1 * (K - KSPLIT)) : XA;

    auto load_tile = [&](int kt, int buf) {
        const int k0 = kt * 16;
        // ---- As: W rows m0..m0+127, one row per thread, transposed store ----
        const float* wrow = W + (size_t)(m0 + tid) * K + k0;
        #pragma unroll
        for (int q4 = 0; q4 < 4; q4++) {
            float4 w4 = *(const float4*)&wrow[q4 * 4];
            As[buf][q4 * 4 + 0][tid] = w4.x;
            As[buf][q4 * 4 + 1][tid] = w4.y;
            As[buf][q4 * 4 + 2][tid] = w4.z;
            As[buf][q4 * 4 + 3][tid] = w4.w;
        }
        // ---- Bs ----
        if (k0 < KSPLIT) {
            #pragma unroll
            for (int r = 0; r < 2; r++) {
                const int ii = tid + r * 128;     // 0..255
                const int kl = ii >> 4;           // 0..15
                const int n4 = ii & 15;           // 0..15
                float4 v = *(const float4*)&XAb[(size_t)(k0 + kl) * N1 + n0 + n4 * 4];
                if (BN_A) {
                    const float sc = g_scale[k0 + kl];
                    const float sf = g_shift[k0 + kl];
                    v.x = fmaxf(fmaf(v.x, sc, sf), 0.f);
                    v.y = fmaxf(fmaf(v.y, sc, sf), 0.f);
                    v.z = fmaxf(fmaf(v.z, sc, sf), 0.f);
                    v.w = fmaxf(fmaf(v.w, sc, sf), 0.f);
                }
                *(float4*)&Bs[buf][kl][n4 * 4] = v;
            }
        } else {
            const int CB = (K - KSPLIT) > 0 ? (K - KSPLIT) : 1;
            #pragma unroll
            for (int r = 0; r < 2; r++) {
                const int ii = tid + r * 128;
                const int nl = ii >> 2;           // 0..63
                const int k4 = ii & 3;
                float4 v = *(const float4*)&XBb[(size_t)(n0 + nl) * CB + (k0 - KSPLIT) + k4 * 4];
                Bs[buf][k4 * 4 + 0][nl] = v.x;
                Bs[buf][k4 * 4 + 1][nl] = v.y;
                Bs[buf][k4 * 4 + 2][nl] = v.z;
                Bs[buf][k4 * 4 + 3][nl] = v.w;
            }
        }
    };

    constexpr int NT = K / 16;
    load_tile(0, 0);
    __syncthreads();

    for (int t = 0; t < NT; ++t) {
        if (t + 1 < NT) load_tile(t + 1, (t + 1) & 1);
        const int buf = t & 1;
        #pragma unroll
        for (int kk = 0; kk < 16; ++kk) {
            float4 a0 = *(const float4*)&As[buf][kk][tm * 8];
            float4 a1 = *(const float4*)&As[buf][kk][tm * 8 + 4];
            ulonglong2 b01 = *(const ulonglong2*)&Bs[buf][kk][tn * 8];
            ulonglong2 b23 = *(const ulonglong2*)&Bs[buf][kk][tn * 8 + 4];
            unsigned long long av;
            DUP2(av, a0.x);
            FMA2(acc[0][0], av, b01.x); FMA2(acc[0][1], av, b01.y);
            FMA2(acc[0][2], av, b23.x); FMA2(acc[0][3], av, b23.y);
            DUP2(av, a0.y);
            FMA2(acc[1][0], av, b01.x); FMA2(acc[1][1], av, b01.y);
            FMA2(acc[1][2], av, b23.x); FMA2(acc[1][3], av, b23.y);
            DUP2(av, a0.z);
            FMA2(acc[2][0], av, b01.x); FMA2(acc[2][1], av, b01.y);
            FMA2(acc[2][2], av, b23.x); FMA2(acc[2][3], av, b23.y);
            DUP2(av, a0.w);
            FMA2(acc[3][0], av, b01.x); FMA2(acc[3][1], av, b01.y);
            FMA2(acc[3][2], av, b23.x); FMA2(acc[3][3], av, b23.y);
            DUP2(av, a1.x);
            FMA2(acc[4][0], av, b01.x); FMA2(acc[4][1], av, b01.y);
            FMA2(acc[4][2], av, b23.x); FMA2(acc[4][3], av, b23.y);
            DUP2(av, a1.y);
            FMA2(acc[5][0], av, b01.x); FMA2(acc[5][1], av, b01.y);
            FMA2(acc[5][2], av, b23.x); FMA2(acc[5][3], av, b23.y);
            DUP2(av, a1.z);
            FMA2(acc[6][0], av, b01.x); FMA2(acc[6][1], av, b01.y);
            FMA2(acc[6][2], av, b23.x); FMA2(acc[6][3], av, b23.y);
            DUP2(av, a1.w);
            FMA2(acc[7][0], av, b01.x); FMA2(acc[7][1], av, b01.y);
            FMA2(acc[7][2], av, b23.x); FMA2(acc[7][3], av, b23.y);
        }
        __syncthreads();
    }

    // epilogue: + bias, store 8 rows x 8 cols
    #pragma unroll
    for (int i = 0; i < 8; i++) {
        const int m = m0 + tm * 8 + i;
        const float bi = bias[m];
        float* yrow = Y + ((size_t)b * M_OUT + m) * N1 + n0 + tn * 8;
        float4 v0, v1;
        v0.x = __uint_as_float((unsigned)(acc[i][0] & 0xffffffffULL)) + bi;
        v0.y = __uint_as_float((unsigned)(acc[i][0] >> 32)) + bi;
        v0.z = __uint_as_float((unsigned)(acc[i][1] & 0xffffffffULL)) + bi;
        v0.w = __uint_as_float((unsigned)(acc[i][1] >> 32)) + bi;
        v1.x = __uint_as_float((unsigned)(acc[i][2] & 0xffffffffULL)) + bi;
        v1.y = __uint_as_float((unsigned)(acc[i][2] >> 32)) + bi;
        v1.z = __uint_as_float((unsigned)(acc[i][3] & 0xffffffffULL)) + bi;
        v1.w = __uint_as_float((unsigned)(acc[i][3] >> 32)) + bi;
        *(float4*)&yrow[0] = v0;
        *(float4*)&yrow[4] = v1;
    }
}

// =========================================================================
// 5) BN stats per channel -> scale/shift
// =========================================================================
__global__ void __launch_bounds__(256) bn_stats_kernel(const float* __restrict__ Y,
                                                       const float* __restrict__ gamma,
                                                       const float* __restrict__ beta)
{
    const int o = blockIdx.x;
    const int t = threadIdx.x;
    float s = 0.f, ss = 0.f;
    #pragma unroll
    for (int b = 0; b < BB; ++b) {
        const float* p = Y + ((size_t)b * M_OUT + o) * N1;
        for (int n = t * 4; n < N1; n += 256 * 4) {
            float4 v = *(const float4*)&p[n];
            s += v.x + v.y + v.z + v.w;
            ss = fmaf(v.x, v.x, ss);
            ss = fmaf(v.y, v.y, ss);
            ss = fmaf(v.z, v.z, ss);
            ss = fmaf(v.w, v.w, ss);
        }
    }
    __shared__ float sh[256], sh2[256];
    sh[t] = s; sh2[t] = ss;
    __syncthreads();
    for (int st = 128; st > 0; st >>= 1) {
        if (t < st) { sh[t] += sh[t + st]; sh2[t] += sh2[t + st]; }
        __syncthreads();
    }
    if (t == 0) {
        const float inv = 1.f / (float)(BB * N1);
        float mu  = sh[0] * inv;
        float var = sh2[0] * inv - mu * mu;
        float sc  = gamma[o] * rsqrtf(var + 1e-5f);
        g_scale[o] = sc;
        g_shift[o] = fmaf(-mu, sc, beta[o]);
    }
}

// =========================================================================
// 6) BN apply + ReLU (final output only)
// =========================================================================
__global__ void __launch_bounds__(256) bn_apply_kernel(float* __restrict__ Y)
{
    const size_t base = ((size_t)blockIdx.x * 256 + threadIdx.x) * 4;
    if (base >= (size_t)TOT) return;
    const int o = (int)((base / N1) % M_OUT);
    const float sc = g_scale[o];
    const float sf = g_shift[o];
    float4 v = *(float4*)&Y[base];
    v.x = fmaxf(fmaf(v.x, sc, sf), 0.f);
    v.y = fmaxf(fmaf(v.y, sc, sf), 0.f);
    v.z = fmaxf(fmaf(v.z, sc, sf), 0.f);
    v.w = fmaxf(fmaf(v.w, sc, sf), 0.f);
    *(float4*)&Y[base] = v;
}

// =========================================================================
// launcher
// =========================================================================
extern "C" void kernel_launch(void* const* d_in, const int* in_sizes, int n_in,
                              void* d_out, int out_size)
{
    const float* p1  = (const float*)d_in[0];
    const float* x1  = (const float*)d_in[1];
    const float* p2  = (const float*)d_in[2];
    const float* x2  = (const float*)d_in[3];
    const float* W1  = (const float*)d_in[4];
    const float* b1  = (const float*)d_in[5];
    const float* g1  = (const float*)d_in[6];
    const float* be1 = (const float*)d_in[7];
    const float* W2  = (const float*)d_in[8];
    const float* b2  = (const float*)d_in[9];
    const float* g2  = (const float*)d_in[10];
    const float* be2 = (const float*)d_in[11];
    float* out = (float*)d_out;

    float* interp_t; cudaGetSymbolAddress((void**)&interp_t, g_interp_t);
    float* y1;       cudaGetSymbolAddress((void**)&y1, g_y1);

    // 1) KNN indices + weights
    knn_kernel<<<dim3(N1 / 128, BB), 128>>>(p1, p2);
    // 2) transpose x2
    transpose_x2_kernel<<<dim3(N2 / 32, C2 / 32, BB), dim3(32, 8)>>>(x2);
    // 3) gather interpolated features (B, N1, C2)
    gather_interp_kernel<<<(BB * N1) / 8, 256>>>();
    // 4) GEMM1: [x1 ; interp] -> y1 (raw, bias only)
    gemm_kernel<K1, C1, false><<<dim3(N1 / 64, M_OUT / 128, BB), 128>>>(W1, b1, x1, interp_t, y1);
    // 5) BN1 stats on raw y1 (apply is fused into GEMM2's loader)
    bn_stats_kernel<<<M_OUT, 256>>>(y1, g1, be1);
    // 6) GEMM2: BN1+ReLU applied to y1 on load -> out (raw, bias only)
    gemm_kernel<K2, K2, true><<<dim3(N1 / 64, M_OUT / 128, BB), 128>>>(W2, b2, y1, nullptr, out);
    // 7) BN2 + ReLU on out
    bn_stats_kernel<<<M_OUT, 256>>>(out, g2, be2);
    bn_apply_kernel<<<TOT / 1024, 256>>>(out);
}

// round 8
// speedup vs baseline: 1.7454x; 1.4008x over previous
#include <cuda_runtime.h>
#include <cuda_bf16.h>
#include <cstdint>
#include <math.h>
#include <float.h>

// Problem constants
#define BB 2
#define N1 16384
#define N2 4096
#define C1 128
#define C2 256
#define M_OUT 256
#define K1 384
#define K2 256
#define TOT (BB * M_OUT * N1)

// ---------------- device scratch ----------------
__device__ float g_x2t[BB * N2 * C2];       // x2 transposed (B, N2, C2)
__device__ int   g_idx[BB * N1 * 3];
__device__ float g_w[BB * N1 * 3];
__device__ float g_interp_t[BB * N1 * C2];  // (B, N1, C2) k-contig
__device__ float g_y1[BB * M_OUT * N1];     // (B, 256, N1) n-contig
__device__ float g_scale[M_OUT];
__device__ float g_shift[M_OUT];

// ---------------- helpers ----------------
__device__ __forceinline__ uint32_t smem_u32(const void* p) {
    uint32_t a;
    asm("{ .reg .u64 t; cvta.to.shared.u64 t, %1; cvt.u32.u64 %0, t; }" : "=r"(a) : "l"(p));
    return a;
}
#define LDSM_X4(R, ADDR) \
    asm volatile("ldmatrix.sync.aligned.m8n8.x4.shared.b16 {%0,%1,%2,%3}, [%4];" \
        : "=r"((R)[0]), "=r"((R)[1]), "=r"((R)[2]), "=r"((R)[3]) : "r"(ADDR))
#define MMA16816(C, A, B0, B1) \
    asm volatile("mma.sync.aligned.m16n8k16.row.col.f32.bf16.bf16.f32 " \
        "{%0,%1,%2,%3}, {%4,%5,%6,%7}, {%8,%9}, {%0,%1,%2,%3};" \
        : "+f"((C)[0]), "+f"((C)[1]), "+f"((C)[2]), "+f"((C)[3]) \
        : "r"((A)[0]), "r"((A)[1]), "r"((A)[2]), "r"((A)[3]), "r"(B0), "r"(B1))

__device__ __forceinline__ void split1(float x, __nv_bfloat16& hi, __nv_bfloat16& lo) {
    hi = __float2bfloat16(x);
    lo = __float2bfloat16(x - __bfloat162float(hi));
}
__device__ __forceinline__ void split2(float x, float y, uint32_t& hi, uint32_t& lo) {
    __nv_bfloat16 hx, lx, hy, ly;
    split1(x, hx, lx); split1(y, hy, ly);
    hi = ((uint32_t)__bfloat16_as_ushort(hy) << 16) | __bfloat16_as_ushort(hx);
    lo = ((uint32_t)__bfloat16_as_ushort(ly) << 16) | __bfloat16_as_ushort(lx);
}

// =========================================================================
// 1) KNN — reference-exact distance arithmetic (proven in R3)
// =========================================================================
#define KNN_CHUNK 2048

__global__ void __launch_bounds__(128) knn_kernel(const float* __restrict__ p1,
                                                  const float* __restrict__ p2)
{
    __shared__ float4 s[KNN_CHUNK];

    const int b = blockIdx.y;
    const int n = blockIdx.x * 128 + threadIdx.x;

    const size_t qoff = ((size_t)b * N1 + n) * 3;
    const float qx = p1[qoff + 0];
    const float qy = p1[qoff + 1];
    const float qz = p1[qoff + 2];
    float tq = __fadd_rn(__fmul_rn(qx, qx), __fmul_rn(qy, qy));
    const float qq = __fadd_rn(tq, __fmul_rn(qz, qz));

    float d0 = FLT_MAX, d1 = FLT_MAX, d2 = FLT_MAX;
    int   i0 = 0,       i1 = 0,       i2 = 0;

    const float* p2b = p2 + (size_t)b * N2 * 3;

    #pragma unroll
    for (int chunk = 0; chunk < N2 / KNN_CHUNK; ++chunk) {
        if (chunk > 0) __syncthreads();
        const int jbase = chunk * KNN_CHUNK;
        for (int j = threadIdx.x; j < KNN_CHUNK; j += 128) {
            float x = p2b[(jbase + j) * 3 + 0];
            float y = p2b[(jbase + j) * 3 + 1];
            float z = p2b[(jbase + j) * 3 + 2];
            float t  = __fadd_rn(__fmul_rn(x, x), __fmul_rn(y, y));
            float bb = __fadd_rn(t, __fmul_rn(z, z));
            s[j] = make_float4(x, y, z, bb);
        }
        __syncthreads();

        #pragma unroll 4
        for (int j = 0; j < KNN_CHUNK; ++j) {
            float4 r = s[j];
            float dot = __fmaf_rn(qz, r.z, __fmaf_rn(qy, r.y, __fmul_rn(qx, r.x)));
            float d = __fsub_rn(__fadd_rn(qq, r.w), __fmul_rn(2.0f, dot));
            if (d < d2) {
                const int jg = jbase + j;
                if (d < d1) {
                    d2 = d1; i2 = i1;
                    if (d < d0) { d1 = d0; i1 = i0; d0 = d; i0 = jg; }
                    else        { d1 = d;  i1 = jg; }
                } else {
                    d2 = d; i2 = jg;
                }
            }
        }
    }

    d0 = fmaxf(d0, 0.0f);
    d1 = fmaxf(d1, 0.0f);
    d2 = fmaxf(d2, 0.0f);
    float w0 = 1.f / (d0 + 1e-16f);
    float w1 = 1.f / (d1 + 1e-16f);
    float w2 = 1.f / (d2 + 1e-16f);
    float ws = 1.f / (w0 + w1 + w2);

    const int base = (b * N1 + n) * 3;
    g_w[base + 0] = w0 * ws;
    g_w[base + 1] = w1 * ws;
    g_w[base + 2] = w2 * ws;
    g_idx[base + 0] = i0;
    g_idx[base + 1] = i1;
    g_idx[base + 2] = i2;
}

// =========================================================================
// 2) Transpose x2 (B, C2, N2) -> (B, N2, C2)
// =========================================================================
__global__ void transpose_x2_kernel(const float* __restrict__ x2)
{
    __shared__ float tile[32][33];
    const int b  = blockIdx.z;
    const int c0 = blockIdx.y * 32;
    const int n0 = blockIdx.x * 32;
    const int tx = threadIdx.x;
    const int ty = threadIdx.y;

    #pragma unroll
    for (int i = ty; i < 32; i += 8)
        tile[i][tx] = x2[((size_t)b * C2 + c0 + i) * N2 + n0 + tx];
    __syncthreads();
    #pragma unroll
    for (int i = ty; i < 32; i += 8)
        g_x2t[((size_t)b * N2 + n0 + i) * C2 + c0 + tx] = tile[tx][i];
}

// =========================================================================
// 3) Gather + weighted sum (one warp per query) -> (B, N1, C2) fp32
// =========================================================================
__global__ void __launch_bounds__(256) gather_interp_kernel()
{
    const int q    = blockIdx.x * 8 + (threadIdx.x >> 5);
    const int lane = threadIdx.x & 31;
    const int b = q / N1;
    const int n = q % N1;

    const int base = q * 3;
    const float w0 = g_w[base + 0];
    const float w1 = g_w[base + 1];
    const float w2 = g_w[base + 2];
    const float* f0 = g_x2t + ((size_t)b * N2 + g_idx[base + 0]) * C2;
    const float* f1 = g_x2t + ((size_t)b * N2 + g_idx[base + 1]) * C2;
    const float* f2 = g_x2t + ((size_t)b * N2 + g_idx[base + 2]) * C2;
    float* o = g_interp_t + ((size_t)b * N1 + n) * C2;

    #pragma unroll
    for (int c = lane; c < C2; c += 32)
        o[c] = fmaf(w0, f0[c], fmaf(w1, f1[c], w2 * f2[c]));
}

// =========================================================================
// 4) bf16x3 GEMM via mma.sync.m16n8k16 + ldmatrix.
//    Y[b, m, n] = sum_k W[m,k] X[k,n] + bias[m]
//    XA: (B, KSPLIT, N1) n-contig  |  XB: (B, N1, K-KSPLIT) k-contig
//    BN_A: apply g_scale/g_shift + ReLU to XA elements on load (channel = k)
//    Block tile 128m x 64n, BK=32, 8 warps (4m x 2n), warp tile 32x32.
//    Smem rows: 72 bf16 = 144 B (hi bf16 [0..31], lo [32..63], 8 pad).
// =========================================================================
template<int K, int KSPLIT, bool BN_A>
__global__ void __launch_bounds__(256) gemm_mma_kernel(
    const float* __restrict__ W, const float* __restrict__ bias,
    const float* __restrict__ XA, const float* __restrict__ XB,
    float* __restrict__ Y)
{
    constexpr int BK   = 32;
    constexpr int ROWB = 144;         // bytes per smem row
    constexpr int ASZ  = 128 * ROWB;  // 18432
    constexpr int BSZ  = 64 * ROWB;   //  9216
    constexpr int NT   = K / BK;

    extern __shared__ __align__(16) unsigned char smem[];
    unsigned char* Ab[2] = { smem,             smem + ASZ + BSZ };
    unsigned char* Bb[2] = { smem + ASZ,       smem + 2 * ASZ + BSZ };

    const int tid  = threadIdx.x;
    const int wid  = tid >> 5;
    const int lane = tid & 31;
    const int wm   = wid >> 1;        // 0..3  -> m offset wm*32
    const int wn   = wid & 1;         // 0..1  -> n offset wn*32

    const int b  = blockIdx.z;
    const int n0 = blockIdx.x * 64;
    const int m0 = blockIdx.y * 128;

    const float* XAb = XA + (size_t)b * KSPLIT * N1;
    const float* XBb = (KSPLIT < K) ? (XB + (size_t)b * N1 * (K - KSPLIT)) : XA;

    float acc[2][4][4];
    #pragma unroll
    for (int mt = 0; mt < 2; ++mt)
        #pragma unroll
        for (int nt = 0; nt < 4; ++nt)
            #pragma unroll
            for (int e = 0; e < 4; ++e) acc[mt][nt][e] = 0.f;

    auto load_tile = [&](int kt, int buf) {
        const int k0 = kt * BK;
        unsigned char* As = Ab[buf];
        unsigned char* Bs = Bb[buf];
        // ---- A: W rows m0..m0+127, 32 k -> 1024 float4 over 4 iters ----
        #pragma unroll
        for (int it = 0; it < 4; ++it) {
            const int idx = tid + it * 256;   // 0..1023
            const int r = idx >> 3, q = idx & 7;
            float4 w4 = *(const float4*)&W[(size_t)(m0 + r) * K + k0 + q * 4];
            uint32_t h0, l0, h1, l1;
            split2(w4.x, w4.y, h0, l0);
            split2(w4.z, w4.w, h1, l1);
            *(uint2*)(As + r * ROWB + q * 8)      = make_uint2(h0, h1);
            *(uint2*)(As + r * ROWB + 64 + q * 8) = make_uint2(l0, l1);
        }
        // ---- B: 32 k x 64 n ----
        if (k0 < KSPLIT) {
            // n-contig source: transpose into [n][k] rows
            #pragma unroll
            for (int it = 0; it < 2; ++it) {
                const int idx = tid + it * 256;   // 0..511
                const int kl = idx >> 4, n4 = idx & 15;
                float4 v = *(const float4*)&XAb[(size_t)(k0 + kl) * N1 + n0 + n4 * 4];
                if (BN_A) {
                    const float sc = g_scale[k0 + kl];
                    const float sf = g_shift[k0 + kl];
                    v.x = fmaxf(fmaf(v.x, sc, sf), 0.f);
                    v.y = fmaxf(fmaf(v.y, sc, sf), 0.f);
                    v.z = fmaxf(fmaf(v.z, sc, sf), 0.f);
                    v.w = fmaxf(fmaf(v.w, sc, sf), 0.f);
                }
                const float* vp = &v.x;
                #pragma unroll
                for (int j = 0; j < 4; ++j) {
                    __nv_bfloat16 hi, lo;
                    split1(vp[j], hi, lo);
                    __nv_bfloat16* prow = (__nv_bfloat16*)(Bs + (n4 * 4 + j) * ROWB);
                    prow[kl]      = hi;
                    prow[32 + kl] = lo;
                }
            }
        } else {
            // k-contig source: direct rows
            constexpr int CB = (K - KSPLIT) > 0 ? (K - KSPLIT) : 1;
            #pragma unroll
            for (int it = 0; it < 2; ++it) {
                const int idx = tid + it * 256;   // 0..511
                const int r = idx >> 3, q = idx & 7;
                float4 v = *(const float4*)&XBb[(size_t)(n0 + r) * CB + (k0 - KSPLIT) + q * 4];
                uint32_t h0, l0, h1, l1;
                split2(v.x, v.y, h0, l0);
                split2(v.z, v.w, h1, l1);
                *(uint2*)(Bs + r * ROWB + q * 8)      = make_uint2(h0, h1);
                *(uint2*)(Bs + r * ROWB + 64 + q * 8) = make_uint2(l0, l1);
            }
        }
    };

    // ldmatrix lane addressing
    const int a_row   = (lane & 7) + ((lane >> 3) & 1) * 8;   // row within 16
    const int a_chunk = (lane >> 4) * 16;                     // byte chunk
    const int b_row   = lane & 7;
    const int b_sel   = lane >> 3;                            // 0..3
    const int b_noff  = (b_sel >> 1) * 8;
    const int b_coff  = (b_sel & 1) * 16;

    auto compute = [&](int buf) {
        const uint32_t Asb = smem_u32(Ab[buf]);
        const uint32_t Bsb = smem_u32(Bb[buf]);
        #pragma unroll
        for (int kk = 0; kk < 2; ++kk) {
            uint32_t a_hi[2][4], a_lo[2][4];
            uint32_t b_hi[4][2], b_lo[4][2];
            #pragma unroll
            for (int mt = 0; mt < 2; ++mt) {
                const uint32_t addr = Asb + (wm * 32 + mt * 16 + a_row) * ROWB + kk * 32 + a_chunk;
                LDSM_X4(a_hi[mt], addr);
                LDSM_X4(a_lo[mt], addr + 64);
            }
            #pragma unroll
            for (int g = 0; g < 2; ++g) {
                const uint32_t addr = Bsb + (wn * 32 + g * 16 + b_noff + b_row) * ROWB + kk * 32 + b_coff;
                uint32_t t[4];
                LDSM_X4(t, addr);
                b_hi[2 * g][0] = t[0]; b_hi[2 * g][1] = t[1];
                b_hi[2 * g + 1][0] = t[2]; b_hi[2 * g + 1][1] = t[3];
                LDSM_X4(t, addr + 64);
                b_lo[2 * g][0] = t[0]; b_lo[2 * g][1] = t[1];
                b_lo[2 * g + 1][0] = t[2]; b_lo[2 * g + 1][1] = t[3];
            }
            #pragma unroll
            for (int mt = 0; mt < 2; ++mt)
                #pragma unroll
                for (int nt = 0; nt < 4; ++nt) {
                    MMA16816(acc[mt][nt], a_hi[mt], b_hi[nt][0], b_hi[nt][1]);
                    MMA16816(acc[mt][nt], a_hi[mt], b_lo[nt][0], b_lo[nt][1]);
                    MMA16816(acc[mt][nt], a_lo[mt], b_hi[nt][0], b_hi[nt][1]);
                }
        }
    };

    load_tile(0, 0);
    __syncthreads();
    for (int t = 0; t < NT; ++t) {
        if (t + 1 < NT) load_tile(t + 1, (t + 1) & 1);
        compute(t & 1);
        __syncthreads();
    }

    // ---- epilogue: + bias, direct stores (float2, coalesced per quarter-warp)
    const int lw = lane >> 2;          // 0..7
    const int ln = (lane & 3) * 2;     // 0,2,4,6
    #pragma unroll
    for (int mt = 0; mt < 2; ++mt) {
        #pragma unroll
        for (int h = 0; h < 2; ++h) {
            const int m = m0 + wm * 32 + mt * 16 + lw + h * 8;
            const float bi = bias[m];
            float* yrow = Y + ((size_t)b * M_OUT + m) * N1 + n0 + wn * 32;
            #pragma unroll
            for (int nt = 0; nt < 4; ++nt) {
                float2 v = make_float2(acc[mt][nt][h * 2 + 0] + bi,
                                       acc[mt][nt][h * 2 + 1] + bi);
                *(float2*)&yrow[nt * 8 + ln] = v;
            }
        }
    }
}

// =========================================================================
// 5) BN stats per channel -> scale/shift
// =========================================================================
__global__ void __launch_bounds__(256) bn_stats_kernel(const float* __restrict__ Y,
                                                       const float* __restrict__ gamma,
                                                       const float* __restrict__ beta)
{
    const int o = blockIdx.x;
    const int t = threadIdx.x;
    float s = 0.f, ss = 0.f;
    #pragma unroll
    for (int b = 0; b < BB; ++b) {
        const float* p = Y + ((size_t)b * M_OUT + o) * N1;
        for (int n = t * 4; n < N1; n += 256 * 4) {
            float4 v = *(const float4*)&p[n];
            s += v.x + v.y + v.z + v.w;
            ss = fmaf(v.x, v.x, ss);
            ss = fmaf(v.y, v.y, ss);
            ss = fmaf(v.z, v.z, ss);
            ss = fmaf(v.w, v.w, ss);
        }
    }
    __shared__ float sh[256], sh2[256];
    sh[t] = s; sh2[t] = ss;
    __syncthreads();
    for (int st = 128; st > 0; st >>= 1) {
        if (t < st) { sh[t] += sh[t + st]; sh2[t] += sh2[t + st]; }
        __syncthreads();
    }
    if (t == 0) {
        const float inv = 1.f / (float)(BB * N1);
        float mu  = sh[0] * inv;
        float var = sh2[0] * inv - mu * mu;
        float sc  = gamma[o] * rsqrtf(var + 1e-5f);
        g_scale[o] = sc;
        g_shift[o] = fmaf(-mu, sc, beta[o]);
    }
}

// =========================================================================
// 6) BN apply + ReLU (final output only)
// =========================================================================
__global__ void __launch_bounds__(256) bn_apply_kernel(float* __restrict__ Y)
{
    const size_t base = ((size_t)blockIdx.x * 256 + threadIdx.x) * 4;
    if (base >= (size_t)TOT) return;
    const int o = (int)((base / N1) % M_OUT);
    const float sc = g_scale[o];
    const float sf = g_shift[o];
    float4 v = *(float4*)&Y[base];
    v.x = fmaxf(fmaf(v.x, sc, sf), 0.f);
    v.y = fmaxf(fmaf(v.y, sc, sf), 0.f);
    v.z = fmaxf(fmaf(v.z, sc, sf), 0.f);
    v.w = fmaxf(fmaf(v.w, sc, sf), 0.f);
    *(float4*)&Y[base] = v;
}

// =========================================================================
// launcher
// =========================================================================
extern "C" void kernel_launch(void* const* d_in, const int* in_sizes, int n_in,
                              void* d_out, int out_size)
{
    const float* p1  = (const float*)d_in[0];
    const float* x1  = (const float*)d_in[1];
    const float* p2  = (const float*)d_in[2];
    const float* x2  = (const float*)d_in[3];
    const float* W1  = (const float*)d_in[4];
    const float* b1  = (const float*)d_in[5];
    const float* g1  = (const float*)d_in[6];
    const float* be1 = (const float*)d_in[7];
    const float* W2  = (const float*)d_in[8];
    const float* b2  = (const float*)d_in[9];
    const float* g2  = (const float*)d_in[10];
    const float* be2 = (const float*)d_in[11];
    float* out = (float*)d_out;

    float* interp_t; cudaGetSymbolAddress((void**)&interp_t, g_interp_t);
    float* y1;       cudaGetSymbolAddress((void**)&y1, g_y1);

    const int smem_bytes = 2 * (128 * 144 + 64 * 144);  // 55296
    cudaFuncSetAttribute(gemm_mma_kernel<K1, C1, false>,
                         cudaFuncAttributeMaxDynamicSharedMemorySize, smem_bytes);
    cudaFuncSetAttribute(gemm_mma_kernel<K2, K2, true>,
                         cudaFuncAttributeMaxDynamicSharedMemorySize, smem_bytes);

    // 1) KNN
    knn_kernel<<<dim3(N1 / 128, BB), 128>>>(p1, p2);
    // 2) transpose x2
    transpose_x2_kernel<<<dim3(N2 / 32, C2 / 32, BB), dim3(32, 8)>>>(x2);
    // 3) gather interp (B, N1, C2)
    gather_interp_kernel<<<(BB * N1) / 8, 256>>>();
    // 4) GEMM1: [x1 ; interp] -> y1 (raw + bias)
    gemm_mma_kernel<K1, C1, false><<<dim3(N1 / 64, 2, BB), 256, smem_bytes>>>(W1, b1, x1, interp_t, y1);
    // 5) BN1 stats (apply fused into GEMM2 loader)
    bn_stats_kernel<<<M_OUT, 256>>>(y1, g1, be1);
    // 6) GEMM2: BN1(y1)+ReLU -> out (raw + bias)
    gemm_mma_kernel<K2, K2, true><<<dim3(N1 / 64, 2, BB), 256, smem_bytes>>>(W2, b2, y1, nullptr, out);
    // 7) BN2 + ReLU
    bn_stats_kernel<<<M_OUT, 256>>>(out, g2, be2);
    bn_apply_kernel<<<TOT / 1024, 256>>>(out);
}